// round 13
// baseline (speedup 1.0000x reference)
#include <cuda_runtime.h>
#include <cuda_fp16.h>
#include <cstdint>

// SplineGCN round 12 (base = R9 config: NPB=48, 1024 thr, fused 123.3us):
//   - phase-2 inner loop rewritten with HFMA2 half2 accumulation (3x fewer issue slots)
//   - everything else identical to the best-measured configuration
//   K1 histprep : col/row histograms + weight permute + zero out + zero scan flags
//   K2 scan     : decoupled-lookback exclusive scan -> startc/curc (self-cleans g_hist)
//   K3 scatter  : packed col-sorted records (1 returning atomic/edge)
//   K4 fused    : 48-node Z tile (fp16, smem) via mma.sync, HFMA2 edge gather,
//                 red.global.add.v4.f32 into out
//   K5 final    : out = out/deg + bias (self-cleans g_degi)

#define MAXN 50176            // 196 * 256
#define MAXE 1605632
#define KO 2048               // 64 kernels * 32 out
#define NPB 48                // source nodes per fused block
#define ZS 2056               // smem Z row stride in halfs (4112B)
#define NCHUNK 196            // MAXN / 256

__device__ uint32_t g_Bperm[16 * KO];
__device__ int      g_hist[MAXN];
__device__ int      g_degi[MAXN];
__device__ int      g_startc[MAXN];
__device__ int      g_curc[MAXN];
__device__ unsigned long long g_desc[NCHUNK];
__device__ uint4    g_rec[MAXE];        // {row, q0|q1, q2|base<<16, col}

static __device__ __forceinline__ uint32_t h2u(__half2 h) {
    return *reinterpret_cast<uint32_t*>(&h);
}

// ---------------- K1: histograms + weight permute + zero out + zero flags ----------------
__global__ void histprep_kernel(const int* __restrict__ ei,
                                const float* __restrict__ w,
                                float* __restrict__ out,
                                int E, int n, int HB) {
    int b = blockIdx.x;
    if (b < HB) {
        int e = b * 256 + threadIdx.x;
        if (e < E) {
            atomicAdd(&g_hist[ei[E + e]], 1);
            atomicAdd(&g_degi[ei[e]], 1);
        }
    } else if (b < HB + 128) {
        int i = (b - HB) * 256 + threadIdx.x;
        int kk = i >> 11, cc = i & 2047;
        int k = cc >> 5, o = cc & 31;
        float w0 = w[k * 1024 + (2 * kk) * 32 + o];
        float w1 = w[k * 1024 + (2 * kk + 1) * 32 + o];
        g_Bperm[i] = h2u(__floats2half2_rn(w0, w1));
    } else if (b == HB + 128) {
        int i = threadIdx.x;
        if (i < NCHUNK) g_desc[i] = 0ull;
    } else {
        int i = (b - HB - 129) * 256 + threadIdx.x;
        if (i < n * 32) out[i] = 0.0f;
    }
}

// ---------------- K2: decoupled-lookback exclusive scan ----------------
__global__ void __launch_bounds__(256) scan_kernel() {
    __shared__ int sh[256];
    __shared__ int s_prefix;
    int b = blockIdx.x, t = threadIdx.x;
    int i = b * 256 + t;
    int v = g_hist[i];
    sh[t] = v; __syncthreads();
#pragma unroll
    for (int o = 1; o < 256; o <<= 1) {
        int u = (t >= o) ? sh[t - o] : 0;
        __syncthreads();
        sh[t] += u;
        __syncthreads();
    }
    int incl = sh[t];
    int total = sh[255];

    if (t < 32) {
        if (b == 0) {
            if (t == 0) {
                unsigned long long w = ((unsigned long long)(unsigned)total << 32) | 2ull;
                atomicExch(&g_desc[0], w);
                s_prefix = 0;
            }
        } else {
            if (t == 0) {
                unsigned long long w = ((unsigned long long)(unsigned)total << 32) | 1ull;
                atomicExch(&g_desc[b], w);
            }
            __syncwarp();
            int exPre = 0;
            int pos = b - 1;
            for (;;) {
                int idx = pos - t;
                unsigned long long w = 0;
                unsigned flag = 1;
                unsigned val = 0;
                if (idx >= 0) {
                    do {
                        w = atomicAdd(&g_desc[idx], 0ull);
                        flag = (unsigned)(w & 3ull);
                    } while (flag == 0);
                    val = (unsigned)(w >> 32);
                }
                unsigned m2 = __ballot_sync(0xFFFFFFFFu, flag == 2u && idx >= 0);
                if (m2) {
                    int j = __ffs(m2) - 1;
                    int contrib = (t <= j) ? (int)val : 0;
#pragma unroll
                    for (int o = 16; o > 0; o >>= 1)
                        contrib += __shfl_down_sync(0xFFFFFFFFu, contrib, o);
                    exPre += __shfl_sync(0xFFFFFFFFu, contrib, 0);
                    break;
                } else {
                    int contrib = (idx >= 0) ? (int)val : 0;
#pragma unroll
                    for (int o = 16; o > 0; o >>= 1)
                        contrib += __shfl_down_sync(0xFFFFFFFFu, contrib, o);
                    exPre += __shfl_sync(0xFFFFFFFFu, contrib, 0);
                    pos -= 32;
                    if (pos < 0) break;
                }
            }
            if (t == 0) {
                unsigned long long w =
                    ((unsigned long long)(unsigned)(exPre + total) << 32) | 2ull;
                atomicExch(&g_desc[b], w);
                s_prefix = exPre;
            }
        }
    }
    __syncthreads();
    int ex = incl - v + s_prefix;
    g_startc[i] = ex;
    g_curc[i] = ex;
    g_hist[i] = 0;
}

// ---------------- K3: scatter into col-sorted, packed records ----------------
__global__ void scatter_kernel(const float* __restrict__ pseudo,
                               const int* __restrict__ ei, int E) {
    int e = blockIdx.x * blockDim.x + threadIdx.x;
    if (e >= E) return;
    int row = ei[e];
    int col = ei[E + e];

    float v0 = pseudo[e * 3 + 0] * 3.0f;
    float v1 = pseudo[e * 3 + 1] * 3.0f;
    float v2 = pseudo[e * 3 + 2] * 3.0f;
    int b0 = (int)v0; b0 = b0 > 2 ? 2 : b0;
    int b1 = (int)v1; b1 = b1 > 2 ? 2 : b1;
    int b2 = (int)v2; b2 = b2 > 2 ? 2 : b2;
    float f0 = v0 - (float)b0, f1 = v1 - (float)b1, f2 = v2 - (float)b2;
    int base = b0 + (b1 << 2) + (b2 << 4);

    int q0 = min((int)(f0 * 65536.0f), 65535);
    int q1 = min((int)(f1 * 65536.0f), 65535);
    int q2 = min((int)(f2 * 65536.0f), 65535);

    int posc = atomicAdd(&g_curc[col], 1);
    g_rec[posc] = make_uint4((uint32_t)row,
                             (uint32_t)q0 | ((uint32_t)q1 << 16),
                             (uint32_t)q2 | ((uint32_t)base << 16),
                             (uint32_t)col);
}

static __device__ __forceinline__ uint32_t lda(const float* __restrict__ f, int r, int c, int n) {
    if (r >= n) return 0u;
    float2 v = *reinterpret_cast<const float2*>(f + (size_t)r * 32 + c);
    return h2u(__floats2half2_rn(v.x, v.y));
}

// ---------------- K4: fused Z tile + HFMA2 edge gather + red scatter ----------------
__global__ void __launch_bounds__(1024) fused_kernel(const float* __restrict__ feat,
                                                     float* __restrict__ out, int n, int E) {
    extern __shared__ uint32_t sZ32[];          // NPB rows * ZS halfs
    const int tid = threadIdx.x;
    const int warp = tid >> 5, lane = tid & 31;
    const int g = lane >> 2, t4 = lane & 3;
    const int nb0 = blockIdx.x * NPB;

    // ---- phase 1: Z[nb0..nb0+48) = feat @ W, fp16 into smem; warp owns 64 cols ----
    uint32_t a[3][2][4];
#pragma unroll
    for (int rg = 0; rg < 3; rg++) {
#pragma unroll
        for (int ks = 0; ks < 2; ks++) {
            int c0 = ks * 16 + t4 * 2;
            int r0 = nb0 + rg * 16 + g;
            a[rg][ks][0] = lda(feat, r0, c0, n);
            a[rg][ks][1] = lda(feat, r0 + 8, c0, n);
            a[rg][ks][2] = lda(feat, r0, c0 + 8, n);
            a[rg][ks][3] = lda(feat, r0 + 8, c0 + 8, n);
        }
    }

    const int colbase = warp * 64;
#pragma unroll 4
    for (int nb = 0; nb < 8; nb++) {
        int c = colbase + nb * 8 + g;
        uint32_t b[2][2];
#pragma unroll
        for (int ks = 0; ks < 2; ks++) {
            b[ks][0] = g_Bperm[((ks * 8 + t4) << 11) + c];
            b[ks][1] = g_Bperm[((ks * 8 + t4 + 4) << 11) + c];
        }
#pragma unroll
        for (int rg = 0; rg < 3; rg++) {
            float c0 = 0.f, c1 = 0.f, c2 = 0.f, c3 = 0.f;
#pragma unroll
            for (int ks = 0; ks < 2; ks++) {
                asm volatile(
                    "mma.sync.aligned.m16n8k16.row.col.f32.f16.f16.f32 "
                    "{%0,%1,%2,%3}, {%4,%5,%6,%7}, {%8,%9}, {%0,%1,%2,%3};"
                    : "+f"(c0), "+f"(c1), "+f"(c2), "+f"(c3)
                    : "r"(a[rg][ks][0]), "r"(a[rg][ks][1]), "r"(a[rg][ks][2]), "r"(a[rg][ks][3]),
                      "r"(b[ks][0]), "r"(b[ks][1]));
            }
            int row0 = rg * 16 + g;
            int ch2 = (colbase >> 1) + nb * 4 + t4;
            sZ32[row0 * (ZS / 2) + ch2]       = h2u(__floats2half2_rn(c0, c1));
            sZ32[(row0 + 8) * (ZS / 2) + ch2] = h2u(__floats2half2_rn(c2, c3));
        }
    }
    __syncthreads();

    // ---- phase 2: edges gather from smem with HFMA2 accumulation, red into out ----
    const __half* sZ = reinterpret_cast<const __half*>(sZ32);
    int estart = g_startc[nb0];
    int eend   = g_startc[nb0 + NPB];
    int l4 = tid & 3;

    for (int i = estart + (tid >> 2); i < eend; i += 256) {
        uint4 r = __ldg(&g_rec[i]);
        int row = (int)r.x;
        int local = (int)r.w - nb0;
        const float iq = 1.0f / 65536.0f;
        float f0 = (float)(r.y & 0xFFFF) * iq;
        float f1 = (float)(r.y >> 16) * iq;
        float f2 = (float)(r.z & 0xFFFF) * iq;
        int base = r.z >> 16;

        // 8 trilinear weights as broadcast half2
        float e0 = 1.0f - f0, e1 = 1.0f - f1, e2 = 1.0f - f2;
        float wy00 = e0 * e1, wy10 = f0 * e1, wy01 = e0 * f1, wy11 = f0 * f1;
        __half2 wh[8];
        wh[0] = __float2half2_rn(wy00 * e2);
        wh[1] = __float2half2_rn(wy10 * e2);
        wh[2] = __float2half2_rn(wy01 * e2);
        wh[3] = __float2half2_rn(wy11 * e2);
        wh[4] = __float2half2_rn(wy00 * f2);
        wh[5] = __float2half2_rn(wy10 * f2);
        wh[6] = __float2half2_rn(wy01 * f2);
        wh[7] = __float2half2_rn(wy11 * f2);

        const __half* zp = sZ + local * ZS + l4 * 8;

        __half2 acc0 = __float2half2_rn(0.f);
        __half2 acc1 = acc0, acc2 = acc0, acc3 = acc0;
#pragma unroll
        for (int s = 0; s < 8; s++) {
            int k = base + (s & 1) + ((s & 2) << 1) + ((s & 4) << 2);
            uint4 u = *reinterpret_cast<const uint4*>(zp + (k << 5));
            acc0 = __hfma2(*reinterpret_cast<__half2*>(&u.x), wh[s], acc0);
            acc1 = __hfma2(*reinterpret_cast<__half2*>(&u.y), wh[s], acc1);
            acc2 = __hfma2(*reinterpret_cast<__half2*>(&u.z), wh[s], acc2);
            acc3 = __hfma2(*reinterpret_cast<__half2*>(&u.w), wh[s], acc3);
        }
        float2 p0 = __half22float2(acc0);
        float2 p1 = __half22float2(acc1);
        float2 p2 = __half22float2(acc2);
        float2 p3 = __half22float2(acc3);

        float* dst = out + (size_t)row * 32 + l4 * 8;
        asm volatile("red.global.add.v4.f32 [%0], {%1,%2,%3,%4};"
                     :: "l"(dst), "f"(p0.x), "f"(p0.y), "f"(p1.x), "f"(p1.y) : "memory");
        asm volatile("red.global.add.v4.f32 [%0], {%1,%2,%3,%4};"
                     :: "l"(dst + 4), "f"(p2.x), "f"(p2.y), "f"(p3.x), "f"(p3.y) : "memory");
    }
}

// ---------------- K5: elementwise divide + bias (self-cleans g_degi) ----------------
__global__ void final_kernel(float* __restrict__ out, const float* __restrict__ bias, int n) {
    int i = blockIdx.x * blockDim.x + threadIdx.x;
    if (i >= n * 32) return;
    int node = i >> 5;
    float d = (float)g_degi[node];
    out[i] = out[i] / fmaxf(d, 1.0f) + bias[i & 31];
    if ((i & 31) == 0) g_degi[node] = 0;
}

extern "C" void kernel_launch(void* const* d_in, const int* in_sizes, int n_in,
                              void* d_out, int out_size) {
    const float* feat   = (const float*)d_in[0];
    const float* pseudo = (const float*)d_in[1];
    const float* weight = (const float*)d_in[2];
    const float* bias   = (const float*)d_in[3];
    const int*   ei     = (const int*)d_in[4];
    int n = in_sizes[0] / 32;
    int E = in_sizes[4] / 2;
    float* out = (float*)d_out;

    const int smem_bytes = NPB * ZS * 2;                // 197376 B
    static int configured = 0;
    if (!configured) {
        cudaFuncSetAttribute(fused_kernel, cudaFuncAttributeMaxDynamicSharedMemorySize, smem_bytes);
        configured = 1;
    }

    int HB = (E + 255) / 256;
    int ZB = (n * 32 + 255) / 256;
    histprep_kernel<<<HB + 128 + 1 + ZB, 256>>>(ei, weight, out, E, n, HB);
    scan_kernel<<<NCHUNK, 256>>>();
    scatter_kernel<<<(E + 255) / 256, 256>>>(pseudo, ei, E);
    fused_kernel<<<(n + NPB - 1) / NPB, 1024, smem_bytes>>>(feat, out, n, E);
    final_kernel<<<(n * 32 + 255) / 256, 256>>>(out, bias, n);
}

// round 14
// speedup vs baseline: 1.0220x; 1.0220x over previous
#include <cuda_runtime.h>
#include <cuda_fp16.h>
#include <cstdint>

// SplineGCN round 14 (base = R13, 172.4us; fused 122.3us):
//   - phase 2 software-pipelined: next rec prefetched before current edge's math,
//     corner LDS batched 4+4 so latencies pipeline; acc chains split in half
//   - all shapes identical to R13 (NPB=48, 1024 thr; R10/R11 remaps regressed)
//   K1 histprep : col/row histograms + weight permute + zero out + zero scan flags
//   K2 scan     : decoupled-lookback exclusive scan -> startc/curc (self-cleans g_hist)
//   K3 scatter  : packed col-sorted records (1 returning atomic/edge)
//   K4 fused    : 48-node Z tile (fp16, smem) via mma.sync, pipelined HFMA2 gather,
//                 red.global.add.v4.f32 into out
//   K5 final    : out = out/deg + bias (self-cleans g_degi)

#define MAXN 50176            // 196 * 256
#define MAXE 1605632
#define KO 2048               // 64 kernels * 32 out
#define NPB 48                // source nodes per fused block
#define ZS 2056               // smem Z row stride in halfs (4112B)
#define NCHUNK 196            // MAXN / 256

__device__ uint32_t g_Bperm[16 * KO];
__device__ int      g_hist[MAXN];
__device__ int      g_degi[MAXN];
__device__ int      g_startc[MAXN];
__device__ int      g_curc[MAXN];
__device__ unsigned long long g_desc[NCHUNK];
__device__ uint4    g_rec[MAXE];        // {row, q0|q1, q2|base<<16, col}

static __device__ __forceinline__ uint32_t h2u(__half2 h) {
    return *reinterpret_cast<uint32_t*>(&h);
}

// ---------------- K1: histograms + weight permute + zero out + zero flags ----------------
__global__ void histprep_kernel(const int* __restrict__ ei,
                                const float* __restrict__ w,
                                float* __restrict__ out,
                                int E, int n, int HB) {
    int b = blockIdx.x;
    if (b < HB) {
        int e = b * 256 + threadIdx.x;
        if (e < E) {
            atomicAdd(&g_hist[ei[E + e]], 1);
            atomicAdd(&g_degi[ei[e]], 1);
        }
    } else if (b < HB + 128) {
        int i = (b - HB) * 256 + threadIdx.x;
        int kk = i >> 11, cc = i & 2047;
        int k = cc >> 5, o = cc & 31;
        float w0 = w[k * 1024 + (2 * kk) * 32 + o];
        float w1 = w[k * 1024 + (2 * kk + 1) * 32 + o];
        g_Bperm[i] = h2u(__floats2half2_rn(w0, w1));
    } else if (b == HB + 128) {
        int i = threadIdx.x;
        if (i < NCHUNK) g_desc[i] = 0ull;
    } else {
        int i = (b - HB - 129) * 256 + threadIdx.x;
        if (i < n * 32) out[i] = 0.0f;
    }
}

// ---------------- K2: decoupled-lookback exclusive scan ----------------
__global__ void __launch_bounds__(256) scan_kernel() {
    __shared__ int sh[256];
    __shared__ int s_prefix;
    int b = blockIdx.x, t = threadIdx.x;
    int i = b * 256 + t;
    int v = g_hist[i];
    sh[t] = v; __syncthreads();
#pragma unroll
    for (int o = 1; o < 256; o <<= 1) {
        int u = (t >= o) ? sh[t - o] : 0;
        __syncthreads();
        sh[t] += u;
        __syncthreads();
    }
    int incl = sh[t];
    int total = sh[255];

    if (t < 32) {
        if (b == 0) {
            if (t == 0) {
                unsigned long long w = ((unsigned long long)(unsigned)total << 32) | 2ull;
                atomicExch(&g_desc[0], w);
                s_prefix = 0;
            }
        } else {
            if (t == 0) {
                unsigned long long w = ((unsigned long long)(unsigned)total << 32) | 1ull;
                atomicExch(&g_desc[b], w);
            }
            __syncwarp();
            int exPre = 0;
            int pos = b - 1;
            for (;;) {
                int idx = pos - t;
                unsigned long long w = 0;
                unsigned flag = 1;
                unsigned val = 0;
                if (idx >= 0) {
                    do {
                        w = atomicAdd(&g_desc[idx], 0ull);
                        flag = (unsigned)(w & 3ull);
                    } while (flag == 0);
                    val = (unsigned)(w >> 32);
                }
                unsigned m2 = __ballot_sync(0xFFFFFFFFu, flag == 2u && idx >= 0);
                if (m2) {
                    int j = __ffs(m2) - 1;
                    int contrib = (t <= j) ? (int)val : 0;
#pragma unroll
                    for (int o = 16; o > 0; o >>= 1)
                        contrib += __shfl_down_sync(0xFFFFFFFFu, contrib, o);
                    exPre += __shfl_sync(0xFFFFFFFFu, contrib, 0);
                    break;
                } else {
                    int contrib = (idx >= 0) ? (int)val : 0;
#pragma unroll
                    for (int o = 16; o > 0; o >>= 1)
                        contrib += __shfl_down_sync(0xFFFFFFFFu, contrib, o);
                    exPre += __shfl_sync(0xFFFFFFFFu, contrib, 0);
                    pos -= 32;
                    if (pos < 0) break;
                }
            }
            if (t == 0) {
                unsigned long long w =
                    ((unsigned long long)(unsigned)(exPre + total) << 32) | 2ull;
                atomicExch(&g_desc[b], w);
                s_prefix = exPre;
            }
        }
    }
    __syncthreads();
    int ex = incl - v + s_prefix;
    g_startc[i] = ex;
    g_curc[i] = ex;
    g_hist[i] = 0;
}

// ---------------- K3: scatter into col-sorted, packed records ----------------
__global__ void scatter_kernel(const float* __restrict__ pseudo,
                               const int* __restrict__ ei, int E) {
    int e = blockIdx.x * blockDim.x + threadIdx.x;
    if (e >= E) return;
    int row = ei[e];
    int col = ei[E + e];

    float v0 = pseudo[e * 3 + 0] * 3.0f;
    float v1 = pseudo[e * 3 + 1] * 3.0f;
    float v2 = pseudo[e * 3 + 2] * 3.0f;
    int b0 = (int)v0; b0 = b0 > 2 ? 2 : b0;
    int b1 = (int)v1; b1 = b1 > 2 ? 2 : b1;
    int b2 = (int)v2; b2 = b2 > 2 ? 2 : b2;
    float f0 = v0 - (float)b0, f1 = v1 - (float)b1, f2 = v2 - (float)b2;
    int base = b0 + (b1 << 2) + (b2 << 4);

    int q0 = min((int)(f0 * 65536.0f), 65535);
    int q1 = min((int)(f1 * 65536.0f), 65535);
    int q2 = min((int)(f2 * 65536.0f), 65535);

    int posc = atomicAdd(&g_curc[col], 1);
    g_rec[posc] = make_uint4((uint32_t)row,
                             (uint32_t)q0 | ((uint32_t)q1 << 16),
                             (uint32_t)q2 | ((uint32_t)base << 16),
                             (uint32_t)col);
}

static __device__ __forceinline__ uint32_t lda(const float* __restrict__ f, int r, int c, int n) {
    if (r >= n) return 0u;
    float2 v = *reinterpret_cast<const float2*>(f + (size_t)r * 32 + c);
    return h2u(__floats2half2_rn(v.x, v.y));
}

// ---------------- K4: fused Z tile + pipelined HFMA2 gather + red scatter ----------------
__global__ void __launch_bounds__(1024) fused_kernel(const float* __restrict__ feat,
                                                     float* __restrict__ out, int n, int E) {
    extern __shared__ uint32_t sZ32[];          // NPB rows * ZS halfs
    const int tid = threadIdx.x;
    const int warp = tid >> 5, lane = tid & 31;
    const int g = lane >> 2, t4 = lane & 3;
    const int nb0 = blockIdx.x * NPB;

    // ---- phase 1: Z[nb0..nb0+48) = feat @ W, fp16 into smem; warp owns 64 cols ----
    uint32_t a[3][2][4];
#pragma unroll
    for (int rg = 0; rg < 3; rg++) {
#pragma unroll
        for (int ks = 0; ks < 2; ks++) {
            int c0 = ks * 16 + t4 * 2;
            int r0 = nb0 + rg * 16 + g;
            a[rg][ks][0] = lda(feat, r0, c0, n);
            a[rg][ks][1] = lda(feat, r0 + 8, c0, n);
            a[rg][ks][2] = lda(feat, r0, c0 + 8, n);
            a[rg][ks][3] = lda(feat, r0 + 8, c0 + 8, n);
        }
    }

    const int colbase = warp * 64;
#pragma unroll 4
    for (int nb = 0; nb < 8; nb++) {
        int c = colbase + nb * 8 + g;
        uint32_t b[2][2];
#pragma unroll
        for (int ks = 0; ks < 2; ks++) {
            b[ks][0] = g_Bperm[((ks * 8 + t4) << 11) + c];
            b[ks][1] = g_Bperm[((ks * 8 + t4 + 4) << 11) + c];
        }
#pragma unroll
        for (int rg = 0; rg < 3; rg++) {
            float c0 = 0.f, c1 = 0.f, c2 = 0.f, c3 = 0.f;
#pragma unroll
            for (int ks = 0; ks < 2; ks++) {
                asm volatile(
                    "mma.sync.aligned.m16n8k16.row.col.f32.f16.f16.f32 "
                    "{%0,%1,%2,%3}, {%4,%5,%6,%7}, {%8,%9}, {%0,%1,%2,%3};"
                    : "+f"(c0), "+f"(c1), "+f"(c2), "+f"(c3)
                    : "r"(a[rg][ks][0]), "r"(a[rg][ks][1]), "r"(a[rg][ks][2]), "r"(a[rg][ks][3]),
                      "r"(b[ks][0]), "r"(b[ks][1]));
            }
            int row0 = rg * 16 + g;
            int ch2 = (colbase >> 1) + nb * 4 + t4;
            sZ32[row0 * (ZS / 2) + ch2]       = h2u(__floats2half2_rn(c0, c1));
            sZ32[(row0 + 8) * (ZS / 2) + ch2] = h2u(__floats2half2_rn(c2, c3));
        }
    }
    __syncthreads();

    // ---- phase 2: software-pipelined edge gather ----
    const __half* sZ = reinterpret_cast<const __half*>(sZ32);
    int estart = g_startc[nb0];
    int eend   = g_startc[nb0 + NPB];
    int l4 = tid & 3;

    int i = estart + (tid >> 2);
    uint4 r;
    if (i < eend) r = __ldg(&g_rec[i]);

    while (i < eend) {
        uint4 cur = r;
        int inext = i + 256;
        if (inext < eend) r = __ldg(&g_rec[inext]);   // prefetch next iteration

        int row = (int)cur.x;
        int local = (int)cur.w - nb0;
        const float iq = 1.0f / 65536.0f;
        float f0 = (float)(cur.y & 0xFFFF) * iq;
        float f1 = (float)(cur.y >> 16) * iq;
        float f2 = (float)(cur.z & 0xFFFF) * iq;
        int base = cur.z >> 16;

        float e0 = 1.0f - f0, e1 = 1.0f - f1, e2 = 1.0f - f2;
        float wy00 = e0 * e1, wy10 = f0 * e1, wy01 = e0 * f1, wy11 = f0 * f1;
        __half2 wh[8];
        wh[0] = __float2half2_rn(wy00 * e2);
        wh[1] = __float2half2_rn(wy10 * e2);
        wh[2] = __float2half2_rn(wy01 * e2);
        wh[3] = __float2half2_rn(wy11 * e2);
        wh[4] = __float2half2_rn(wy00 * f2);
        wh[5] = __float2half2_rn(wy10 * f2);
        wh[6] = __float2half2_rn(wy01 * f2);
        wh[7] = __float2half2_rn(wy11 * f2);

        const __half* zp = sZ + local * ZS + l4 * 8;

        // batch LDS 4 + FMA 4, then LDS 4 + FMA 4 (latencies pipeline within a batch)
        uint4 u[4];
        __half2 acc0 = __float2half2_rn(0.f);
        __half2 acc1 = acc0, acc2 = acc0, acc3 = acc0;
        __half2 bcc0 = acc0, bcc1 = acc0, bcc2 = acc0, bcc3 = acc0;
#pragma unroll
        for (int s = 0; s < 4; s++) {
            int k = base + (s & 1) + ((s & 2) << 1);
            u[s] = *reinterpret_cast<const uint4*>(zp + (k << 5));
        }
#pragma unroll
        for (int s = 0; s < 4; s++) {
            acc0 = __hfma2(*reinterpret_cast<__half2*>(&u[s].x), wh[s], acc0);
            acc1 = __hfma2(*reinterpret_cast<__half2*>(&u[s].y), wh[s], acc1);
            acc2 = __hfma2(*reinterpret_cast<__half2*>(&u[s].z), wh[s], acc2);
            acc3 = __hfma2(*reinterpret_cast<__half2*>(&u[s].w), wh[s], acc3);
        }
#pragma unroll
        for (int s = 0; s < 4; s++) {
            int k = base + (s & 1) + ((s & 2) << 1) + 16;
            u[s] = *reinterpret_cast<const uint4*>(zp + (k << 5));
        }
#pragma unroll
        for (int s = 0; s < 4; s++) {
            bcc0 = __hfma2(*reinterpret_cast<__half2*>(&u[s].x), wh[s + 4], bcc0);
            bcc1 = __hfma2(*reinterpret_cast<__half2*>(&u[s].y), wh[s + 4], bcc1);
            bcc2 = __hfma2(*reinterpret_cast<__half2*>(&u[s].z), wh[s + 4], bcc2);
            bcc3 = __hfma2(*reinterpret_cast<__half2*>(&u[s].w), wh[s + 4], bcc3);
        }
        acc0 = __hadd2(acc0, bcc0);
        acc1 = __hadd2(acc1, bcc1);
        acc2 = __hadd2(acc2, bcc2);
        acc3 = __hadd2(acc3, bcc3);

        float2 p0 = __half22float2(acc0);
        float2 p1 = __half22float2(acc1);
        float2 p2 = __half22float2(acc2);
        float2 p3 = __half22float2(acc3);

        float* dst = out + (size_t)row * 32 + l4 * 8;
        asm volatile("red.global.add.v4.f32 [%0], {%1,%2,%3,%4};"
                     :: "l"(dst), "f"(p0.x), "f"(p0.y), "f"(p1.x), "f"(p1.y) : "memory");
        asm volatile("red.global.add.v4.f32 [%0], {%1,%2,%3,%4};"
                     :: "l"(dst + 4), "f"(p2.x), "f"(p2.y), "f"(p3.x), "f"(p3.y) : "memory");

        i = inext;
    }
}

// ---------------- K5: elementwise divide + bias (self-cleans g_degi) ----------------
__global__ void final_kernel(float* __restrict__ out, const float* __restrict__ bias, int n) {
    int i = blockIdx.x * blockDim.x + threadIdx.x;
    if (i >= n * 32) return;
    int node = i >> 5;
    float d = (float)g_degi[node];
    out[i] = out[i] / fmaxf(d, 1.0f) + bias[i & 31];
    if ((i & 31) == 0) g_degi[node] = 0;
}

extern "C" void kernel_launch(void* const* d_in, const int* in_sizes, int n_in,
                              void* d_out, int out_size) {
    const float* feat   = (const float*)d_in[0];
    const float* pseudo = (const float*)d_in[1];
    const float* weight = (const float*)d_in[2];
    const float* bias   = (const float*)d_in[3];
    const int*   ei     = (const int*)d_in[4];
    int n = in_sizes[0] / 32;
    int E = in_sizes[4] / 2;
    float* out = (float*)d_out;

    const int smem_bytes = NPB * ZS * 2;                // 197376 B
    static int configured = 0;
    if (!configured) {
        cudaFuncSetAttribute(fused_kernel, cudaFuncAttributeMaxDynamicSharedMemorySize, smem_bytes);
        configured = 1;
    }

    int HB = (E + 255) / 256;
    int ZB = (n * 32 + 255) / 256;
    histprep_kernel<<<HB + 128 + 1 + ZB, 256>>>(ei, weight, out, E, n, HB);
    scan_kernel<<<NCHUNK, 256>>>();
    scatter_kernel<<<(E + 255) / 256, 256>>>(pseudo, ei, E);
    fused_kernel<<<(n + NPB - 1) / NPB, 1024, smem_bytes>>>(feat, out, n, E);
    final_kernel<<<(n * 32 + 255) / 256, 256>>>(out, bias, n);
}

// round 15
// speedup vs baseline: 1.0222x; 1.0002x over previous
#include <cuda_runtime.h>
#include <cuda_fp16.h>
#include <cstdint>

// SplineGCN round 14 (base = R13, 172.4us; fused 122.3us):
//   - phase 2 software-pipelined: next rec prefetched before current edge's math,
//     corner LDS batched 4+4 so latencies pipeline; acc chains split in half
//   - all shapes identical to R13 (NPB=48, 1024 thr; R10/R11 remaps regressed)
//   K1 histprep : col/row histograms + weight permute + zero out + zero scan flags
//   K2 scan     : decoupled-lookback exclusive scan -> startc/curc (self-cleans g_hist)
//   K3 scatter  : packed col-sorted records (1 returning atomic/edge)
//   K4 fused    : 48-node Z tile (fp16, smem) via mma.sync, pipelined HFMA2 gather,
//                 red.global.add.v4.f32 into out
//   K5 final    : out = out/deg + bias (self-cleans g_degi)

#define MAXN 50176            // 196 * 256
#define MAXE 1605632
#define KO 2048               // 64 kernels * 32 out
#define NPB 48                // source nodes per fused block
#define ZS 2056               // smem Z row stride in halfs (4112B)
#define NCHUNK 196            // MAXN / 256

__device__ uint32_t g_Bperm[16 * KO];
__device__ int      g_hist[MAXN];
__device__ int      g_degi[MAXN];
__device__ int      g_startc[MAXN];
__device__ int      g_curc[MAXN];
__device__ unsigned long long g_desc[NCHUNK];
__device__ uint4    g_rec[MAXE];        // {row, q0|q1, q2|base<<16, col}

static __device__ __forceinline__ uint32_t h2u(__half2 h) {
    return *reinterpret_cast<uint32_t*>(&h);
}

// ---------------- K1: histograms + weight permute + zero out + zero flags ----------------
__global__ void histprep_kernel(const int* __restrict__ ei,
                                const float* __restrict__ w,
                                float* __restrict__ out,
                                int E, int n, int HB) {
    int b = blockIdx.x;
    if (b < HB) {
        int e = b * 256 + threadIdx.x;
        if (e < E) {
            atomicAdd(&g_hist[ei[E + e]], 1);
            atomicAdd(&g_degi[ei[e]], 1);
        }
    } else if (b < HB + 128) {
        int i = (b - HB) * 256 + threadIdx.x;
        int kk = i >> 11, cc = i & 2047;
        int k = cc >> 5, o = cc & 31;
        float w0 = w[k * 1024 + (2 * kk) * 32 + o];
        float w1 = w[k * 1024 + (2 * kk + 1) * 32 + o];
        g_Bperm[i] = h2u(__floats2half2_rn(w0, w1));
    } else if (b == HB + 128) {
        int i = threadIdx.x;
        if (i < NCHUNK) g_desc[i] = 0ull;
    } else {
        int i = (b - HB - 129) * 256 + threadIdx.x;
        if (i < n * 32) out[i] = 0.0f;
    }
}

// ---------------- K2: decoupled-lookback exclusive scan ----------------
__global__ void __launch_bounds__(256) scan_kernel() {
    __shared__ int sh[256];
    __shared__ int s_prefix;
    int b = blockIdx.x, t = threadIdx.x;
    int i = b * 256 + t;
    int v = g_hist[i];
    sh[t] = v; __syncthreads();
#pragma unroll
    for (int o = 1; o < 256; o <<= 1) {
        int u = (t >= o) ? sh[t - o] : 0;
        __syncthreads();
        sh[t] += u;
        __syncthreads();
    }
    int incl = sh[t];
    int total = sh[255];

    if (t < 32) {
        if (b == 0) {
            if (t == 0) {
                unsigned long long w = ((unsigned long long)(unsigned)total << 32) | 2ull;
                atomicExch(&g_desc[0], w);
                s_prefix = 0;
            }
        } else {
            if (t == 0) {
                unsigned long long w = ((unsigned long long)(unsigned)total << 32) | 1ull;
                atomicExch(&g_desc[b], w);
            }
            __syncwarp();
            int exPre = 0;
            int pos = b - 1;
            for (;;) {
                int idx = pos - t;
                unsigned long long w = 0;
                unsigned flag = 1;
                unsigned val = 0;
                if (idx >= 0) {
                    do {
                        w = atomicAdd(&g_desc[idx], 0ull);
                        flag = (unsigned)(w & 3ull);
                    } while (flag == 0);
                    val = (unsigned)(w >> 32);
                }
                unsigned m2 = __ballot_sync(0xFFFFFFFFu, flag == 2u && idx >= 0);
                if (m2) {
                    int j = __ffs(m2) - 1;
                    int contrib = (t <= j) ? (int)val : 0;
#pragma unroll
                    for (int o = 16; o > 0; o >>= 1)
                        contrib += __shfl_down_sync(0xFFFFFFFFu, contrib, o);
                    exPre += __shfl_sync(0xFFFFFFFFu, contrib, 0);
                    break;
                } else {
                    int contrib = (idx >= 0) ? (int)val : 0;
#pragma unroll
                    for (int o = 16; o > 0; o >>= 1)
                        contrib += __shfl_down_sync(0xFFFFFFFFu, contrib, o);
                    exPre += __shfl_sync(0xFFFFFFFFu, contrib, 0);
                    pos -= 32;
                    if (pos < 0) break;
                }
            }
            if (t == 0) {
                unsigned long long w =
                    ((unsigned long long)(unsigned)(exPre + total) << 32) | 2ull;
                atomicExch(&g_desc[b], w);
                s_prefix = exPre;
            }
        }
    }
    __syncthreads();
    int ex = incl - v + s_prefix;
    g_startc[i] = ex;
    g_curc[i] = ex;
    g_hist[i] = 0;
}

// ---------------- K3: scatter into col-sorted, packed records ----------------
__global__ void scatter_kernel(const float* __restrict__ pseudo,
                               const int* __restrict__ ei, int E) {
    int e = blockIdx.x * blockDim.x + threadIdx.x;
    if (e >= E) return;
    int row = ei[e];
    int col = ei[E + e];

    float v0 = pseudo[e * 3 + 0] * 3.0f;
    float v1 = pseudo[e * 3 + 1] * 3.0f;
    float v2 = pseudo[e * 3 + 2] * 3.0f;
    int b0 = (int)v0; b0 = b0 > 2 ? 2 : b0;
    int b1 = (int)v1; b1 = b1 > 2 ? 2 : b1;
    int b2 = (int)v2; b2 = b2 > 2 ? 2 : b2;
    float f0 = v0 - (float)b0, f1 = v1 - (float)b1, f2 = v2 - (float)b2;
    int base = b0 + (b1 << 2) + (b2 << 4);

    int q0 = min((int)(f0 * 65536.0f), 65535);
    int q1 = min((int)(f1 * 65536.0f), 65535);
    int q2 = min((int)(f2 * 65536.0f), 65535);

    int posc = atomicAdd(&g_curc[col], 1);
    g_rec[posc] = make_uint4((uint32_t)row,
                             (uint32_t)q0 | ((uint32_t)q1 << 16),
                             (uint32_t)q2 | ((uint32_t)base << 16),
                             (uint32_t)col);
}

static __device__ __forceinline__ uint32_t lda(const float* __restrict__ f, int r, int c, int n) {
    if (r >= n) return 0u;
    float2 v = *reinterpret_cast<const float2*>(f + (size_t)r * 32 + c);
    return h2u(__floats2half2_rn(v.x, v.y));
}

// ---------------- K4: fused Z tile + pipelined HFMA2 gather + red scatter ----------------
__global__ void __launch_bounds__(1024) fused_kernel(const float* __restrict__ feat,
                                                     float* __restrict__ out, int n, int E) {
    extern __shared__ uint32_t sZ32[];          // NPB rows * ZS halfs
    const int tid = threadIdx.x;
    const int warp = tid >> 5, lane = tid & 31;
    const int g = lane >> 2, t4 = lane & 3;
    const int nb0 = blockIdx.x * NPB;

    // ---- phase 1: Z[nb0..nb0+48) = feat @ W, fp16 into smem; warp owns 64 cols ----
    uint32_t a[3][2][4];
#pragma unroll
    for (int rg = 0; rg < 3; rg++) {
#pragma unroll
        for (int ks = 0; ks < 2; ks++) {
            int c0 = ks * 16 + t4 * 2;
            int r0 = nb0 + rg * 16 + g;
            a[rg][ks][0] = lda(feat, r0, c0, n);
            a[rg][ks][1] = lda(feat, r0 + 8, c0, n);
            a[rg][ks][2] = lda(feat, r0, c0 + 8, n);
            a[rg][ks][3] = lda(feat, r0 + 8, c0 + 8, n);
        }
    }

    const int colbase = warp * 64;
#pragma unroll 4
    for (int nb = 0; nb < 8; nb++) {
        int c = colbase + nb * 8 + g;
        uint32_t b[2][2];
#pragma unroll
        for (int ks = 0; ks < 2; ks++) {
            b[ks][0] = g_Bperm[((ks * 8 + t4) << 11) + c];
            b[ks][1] = g_Bperm[((ks * 8 + t4 + 4) << 11) + c];
        }
#pragma unroll
        for (int rg = 0; rg < 3; rg++) {
            float c0 = 0.f, c1 = 0.f, c2 = 0.f, c3 = 0.f;
#pragma unroll
            for (int ks = 0; ks < 2; ks++) {
                asm volatile(
                    "mma.sync.aligned.m16n8k16.row.col.f32.f16.f16.f32 "
                    "{%0,%1,%2,%3}, {%4,%5,%6,%7}, {%8,%9}, {%0,%1,%2,%3};"
                    : "+f"(c0), "+f"(c1), "+f"(c2), "+f"(c3)
                    : "r"(a[rg][ks][0]), "r"(a[rg][ks][1]), "r"(a[rg][ks][2]), "r"(a[rg][ks][3]),
                      "r"(b[ks][0]), "r"(b[ks][1]));
            }
            int row0 = rg * 16 + g;
            int ch2 = (colbase >> 1) + nb * 4 + t4;
            sZ32[row0 * (ZS / 2) + ch2]       = h2u(__floats2half2_rn(c0, c1));
            sZ32[(row0 + 8) * (ZS / 2) + ch2] = h2u(__floats2half2_rn(c2, c3));
        }
    }
    __syncthreads();

    // ---- phase 2: software-pipelined edge gather ----
    const __half* sZ = reinterpret_cast<const __half*>(sZ32);
    int estart = g_startc[nb0];
    int eend   = g_startc[nb0 + NPB];
    int l4 = tid & 3;

    int i = estart + (tid >> 2);
    uint4 r;
    if (i < eend) r = __ldg(&g_rec[i]);

    while (i < eend) {
        uint4 cur = r;
        int inext = i + 256;
        if (inext < eend) r = __ldg(&g_rec[inext]);   // prefetch next iteration

        int row = (int)cur.x;
        int local = (int)cur.w - nb0;
        const float iq = 1.0f / 65536.0f;
        float f0 = (float)(cur.y & 0xFFFF) * iq;
        float f1 = (float)(cur.y >> 16) * iq;
        float f2 = (float)(cur.z & 0xFFFF) * iq;
        int base = cur.z >> 16;

        float e0 = 1.0f - f0, e1 = 1.0f - f1, e2 = 1.0f - f2;
        float wy00 = e0 * e1, wy10 = f0 * e1, wy01 = e0 * f1, wy11 = f0 * f1;
        __half2 wh[8];
        wh[0] = __float2half2_rn(wy00 * e2);
        wh[1] = __float2half2_rn(wy10 * e2);
        wh[2] = __float2half2_rn(wy01 * e2);
        wh[3] = __float2half2_rn(wy11 * e2);
        wh[4] = __float2half2_rn(wy00 * f2);
        wh[5] = __float2half2_rn(wy10 * f2);
        wh[6] = __float2half2_rn(wy01 * f2);
        wh[7] = __float2half2_rn(wy11 * f2);

        const __half* zp = sZ + local * ZS + l4 * 8;

        // batch LDS 4 + FMA 4, then LDS 4 + FMA 4 (latencies pipeline within a batch)
        uint4 u[4];
        __half2 acc0 = __float2half2_rn(0.f);
        __half2 acc1 = acc0, acc2 = acc0, acc3 = acc0;
        __half2 bcc0 = acc0, bcc1 = acc0, bcc2 = acc0, bcc3 = acc0;
#pragma unroll
        for (int s = 0; s < 4; s++) {
            int k = base + (s & 1) + ((s & 2) << 1);
            u[s] = *reinterpret_cast<const uint4*>(zp + (k << 5));
        }
#pragma unroll
        for (int s = 0; s < 4; s++) {
            acc0 = __hfma2(*reinterpret_cast<__half2*>(&u[s].x), wh[s], acc0);
            acc1 = __hfma2(*reinterpret_cast<__half2*>(&u[s].y), wh[s], acc1);
            acc2 = __hfma2(*reinterpret_cast<__half2*>(&u[s].z), wh[s], acc2);
            acc3 = __hfma2(*reinterpret_cast<__half2*>(&u[s].w), wh[s], acc3);
        }
#pragma unroll
        for (int s = 0; s < 4; s++) {
            int k = base + (s & 1) + ((s & 2) << 1) + 16;
            u[s] = *reinterpret_cast<const uint4*>(zp + (k << 5));
        }
#pragma unroll
        for (int s = 0; s < 4; s++) {
            bcc0 = __hfma2(*reinterpret_cast<__half2*>(&u[s].x), wh[s + 4], bcc0);
            bcc1 = __hfma2(*reinterpret_cast<__half2*>(&u[s].y), wh[s + 4], bcc1);
            bcc2 = __hfma2(*reinterpret_cast<__half2*>(&u[s].z), wh[s + 4], bcc2);
            bcc3 = __hfma2(*reinterpret_cast<__half2*>(&u[s].w), wh[s + 4], bcc3);
        }
        acc0 = __hadd2(acc0, bcc0);
        acc1 = __hadd2(acc1, bcc1);
        acc2 = __hadd2(acc2, bcc2);
        acc3 = __hadd2(acc3, bcc3);

        float2 p0 = __half22float2(acc0);
        float2 p1 = __half22float2(acc1);
        float2 p2 = __half22float2(acc2);
        float2 p3 = __half22float2(acc3);

        float* dst = out + (size_t)row * 32 + l4 * 8;
        asm volatile("red.global.add.v4.f32 [%0], {%1,%2,%3,%4};"
                     :: "l"(dst), "f"(p0.x), "f"(p0.y), "f"(p1.x), "f"(p1.y) : "memory");
        asm volatile("red.global.add.v4.f32 [%0], {%1,%2,%3,%4};"
                     :: "l"(dst + 4), "f"(p2.x), "f"(p2.y), "f"(p3.x), "f"(p3.y) : "memory");

        i = inext;
    }
}

// ---------------- K5: elementwise divide + bias (self-cleans g_degi) ----------------
__global__ void final_kernel(float* __restrict__ out, const float* __restrict__ bias, int n) {
    int i = blockIdx.x * blockDim.x + threadIdx.x;
    if (i >= n * 32) return;
    int node = i >> 5;
    float d = (float)g_degi[node];
    out[i] = out[i] / fmaxf(d, 1.0f) + bias[i & 31];
    if ((i & 31) == 0) g_degi[node] = 0;
}

extern "C" void kernel_launch(void* const* d_in, const int* in_sizes, int n_in,
                              void* d_out, int out_size) {
    const float* feat   = (const float*)d_in[0];
    const float* pseudo = (const float*)d_in[1];
    const float* weight = (const float*)d_in[2];
    const float* bias   = (const float*)d_in[3];
    const int*   ei     = (const int*)d_in[4];
    int n = in_sizes[0] / 32;
    int E = in_sizes[4] / 2;
    float* out = (float*)d_out;

    const int smem_bytes = NPB * ZS * 2;                // 197376 B
    static int configured = 0;
    if (!configured) {
        cudaFuncSetAttribute(fused_kernel, cudaFuncAttributeMaxDynamicSharedMemorySize, smem_bytes);
        configured = 1;
    }

    int HB = (E + 255) / 256;
    int ZB = (n * 32 + 255) / 256;
    histprep_kernel<<<HB + 128 + 1 + ZB, 256>>>(ei, weight, out, E, n, HB);
    scan_kernel<<<NCHUNK, 256>>>();
    scatter_kernel<<<(E + 255) / 256, 256>>>(pseudo, ei, E);
    fused_kernel<<<(n + NPB - 1) / NPB, 1024, smem_bytes>>>(feat, out, n, E);
    final_kernel<<<(n * 32 + 255) / 256, 256>>>(out, bias, n);
}